// round 16
// baseline (speedup 1.0000x reference)
#include <cuda_runtime.h>
#include <cuda_fp16.h>
#include <cstdint>
#include <cstddef>

#define BATCH 64
#define T     4096
#define DIN   128
#define DST   256
#define DOUT  128

// ---------------------------------------------------------------------------
// PTX helpers
// ---------------------------------------------------------------------------
__device__ __forceinline__ uint32_t ctarank() {
    uint32_t r; asm("mov.u32 %0, %%cluster_ctarank;" : "=r"(r)); return r;
}
__device__ __forceinline__ uint32_t smem_u32(const void* p) {
    uint32_t a;
    asm("{ .reg .u64 t; cvta.to.shared.u64 t, %1; cvt.u32.u64 %0, t; }"
        : "=r"(a) : "l"(p));
    return a;
}
__device__ __forceinline__ uint32_t mapa_u32(uint32_t l, uint32_t r) {
    uint32_t v; asm("mapa.shared::cluster.u32 %0, %1, %2;" : "=r"(v) : "r"(l), "r"(r));
    return v;
}
__device__ __forceinline__ void mbar_init(uint32_t m, uint32_t cnt) {
    asm volatile("mbarrier.init.shared.b64 [%0], %1;" :: "r"(m), "r"(cnt) : "memory");
}
__device__ __forceinline__ void mbar_expect(uint32_t m, uint32_t tx) {
    asm volatile("mbarrier.arrive.expect_tx.shared.b64 _, [%0], %1;"
                 :: "r"(m), "r"(tx) : "memory");
}
__device__ __forceinline__ void mbar_wait(uint32_t m, uint32_t parity) {
    asm volatile(
        "{\n\t.reg .pred P;\n\t"
        "W_%=:\n\t"
        "mbarrier.try_wait.parity.acquire.cluster.shared::cta.b64 P, [%0], %1, 0x989680;\n\t"
        "@!P bra W_%=;\n\t}"
        :: "r"(m), "r"(parity) : "memory");
}
__device__ __forceinline__ void st_async_b32(uint32_t raddr, uint32_t val, uint32_t rmbar) {
    asm volatile("st.async.shared::cluster.mbarrier::complete_tx::bytes.b32 [%0], %1, [%2];"
                 :: "r"(raddr), "r"(val), "r"(rmbar) : "memory");
}
#define CLUSTER_SYNC() do { \
    asm volatile("barrier.cluster.arrive.aligned;" ::: "memory"); \
    asm volatile("barrier.cluster.wait.aligned;"   ::: "memory"); \
} while (0)

// Exact identity tanh: 1 - 2/(1+e^{2s}).  |err| ~1e-6 (validated R11-R14).
__device__ __forceinline__ float tanh_fast(float s) {
    float e = __expf(2.0f * s);
    return 1.0f - __fdividef(2.0f, e + 1.0f);
}

// 64 HFMA2 over 128 halfs (16 uint4) into 8 half2 chains (8 adds each)
#define MAC64(ACC, W, XB) do {                                           \
    const uint4* xp_ = (const uint4*)(XB);                               \
    _Pragma("unroll")                                                    \
    for (int j_ = 0; j_ < 16; j_ += 2) {                                 \
        uint4 v0_ = xp_[j_], v1_ = xp_[j_ + 1];                          \
        (ACC)[0] = __hfma2((W)[4*j_+0], *(__half2*)&v0_.x, (ACC)[0]);    \
        (ACC)[1] = __hfma2((W)[4*j_+1], *(__half2*)&v0_.y, (ACC)[1]);    \
        (ACC)[2] = __hfma2((W)[4*j_+2], *(__half2*)&v0_.z, (ACC)[2]);    \
        (ACC)[3] = __hfma2((W)[4*j_+3], *(__half2*)&v0_.w, (ACC)[3]);    \
        (ACC)[4] = __hfma2((W)[4*j_+4], *(__half2*)&v1_.x, (ACC)[4]);    \
        (ACC)[5] = __hfma2((W)[4*j_+5], *(__half2*)&v1_.y, (ACC)[5]);    \
        (ACC)[6] = __hfma2((W)[4*j_+6], *(__half2*)&v1_.z, (ACC)[6]);    \
        (ACC)[7] = __hfma2((W)[4*j_+7], *(__half2*)&v1_.w, (ACC)[7]);    \
    } } while (0)

// 32 HFMA2 over 64 halfs (8 uint4) into 8 half2 chains (4 adds each)
#define MAC32(ACC, W, XB) do {                                           \
    const uint4* xp_ = (const uint4*)(XB);                               \
    _Pragma("unroll")                                                    \
    for (int j_ = 0; j_ < 8; j_ += 2) {                                  \
        uint4 v0_ = xp_[j_], v1_ = xp_[j_ + 1];                          \
        (ACC)[0] = __hfma2((W)[4*j_+0], *(__half2*)&v0_.x, (ACC)[0]);    \
        (ACC)[1] = __hfma2((W)[4*j_+1], *(__half2*)&v0_.y, (ACC)[1]);    \
        (ACC)[2] = __hfma2((W)[4*j_+2], *(__half2*)&v0_.z, (ACC)[2]);    \
        (ACC)[3] = __hfma2((W)[4*j_+3], *(__half2*)&v0_.w, (ACC)[3]);    \
        (ACC)[4] = __hfma2((W)[4*j_+4], *(__half2*)&v1_.x, (ACC)[4]);    \
        (ACC)[5] = __hfma2((W)[4*j_+5], *(__half2*)&v1_.y, (ACC)[5]);    \
        (ACC)[6] = __hfma2((W)[4*j_+6], *(__half2*)&v1_.z, (ACC)[6]);    \
        (ACC)[7] = __hfma2((W)[4*j_+7], *(__half2*)&v1_.w, (ACC)[7]);    \
    } } while (0)

#define ZERO8(ACC) do { _Pragma("unroll") \
    for (int k_ = 0; k_ < 8; k_++) (ACC)[k_] = __float2half2_rn(0.f); } while (0)

__device__ __forceinline__ float hsum8a(const __half2* q) {
    float2 a0 = __half22float2(q[0]), a1 = __half22float2(q[1]);
    float2 a2 = __half22float2(q[2]), a3 = __half22float2(q[3]);
    float2 a4 = __half22float2(q[4]), a5 = __half22float2(q[5]);
    float2 a6 = __half22float2(q[6]), a7 = __half22float2(q[7]);
    return (((a0.x+a0.y)+(a1.x+a1.y)) + ((a2.x+a2.y)+(a3.x+a3.y)))
         + (((a4.x+a4.y)+(a5.x+a5.y)) + ((a6.x+a6.y)+(a7.x+a7.y)));
}

// Shared layout (identical on both CTAs; fixed offsets for remote addressing)
struct __align__(16) SM {
    __half xs[2][256];             // CTA0: local x ring            1024 B
    __half xb[2][256];             // CTA1: received x ring         1024 B
    __half us[2][128];             // CTA1: u staging                512 B
    float  pBu[2][256];            // CTA0: received B.u ring       2048 B
    float  psC[128];               // CTA1: y half-combine           512 B
    unsigned long long mbA[2];     // CTA0: pBu arrival
    unsigned long long mbB[2];     // CTA1: x arrival
};
#define XS_OFF   ((uint32_t)offsetof(SM, xs))
#define XB_OFF   ((uint32_t)offsetof(SM, xb))
#define PBU_OFF  ((uint32_t)offsetof(SM, pBu))
#define MBA_OFF  ((uint32_t)offsetof(SM, mbA))
#define MBB_OFF  ((uint32_t)offsetof(SM, mbB))

// ---------------------------------------------------------------------------
// Pipelined-role SSM (R14 structure, tail-shaved):
// CTA0 (recurrence engine): thread i holds the FULL A row in 128 half2 regs.
//   step t: wait pBu(t) AT THE HEAD (pre-delivered 2 steps early -> fast-path;
//   TRYWAIT overlaps the sibling warp's HFMA2 stream) + preload pBu to reg ->
//   A.x_t (128 HFMA2, CTA-local) -> hsum -> tanh -> st.shared.b16 (own half,
//   no shuffle on the local chain) -> shfl+st.async b32 ship to CTA1 -> bar.
// CTA1 (co-processor): unchanged from R14: B.u_{k+2} matvec; wait x_{k+1};
//   y_k = C.x_{k+1}; ship pBu(k+2) (release token); y store.
// ---------------------------------------------------------------------------
__global__ void __launch_bounds__(256, 1) __cluster_dims__(2, 1, 1)
ssm_fused(const float* __restrict__ u, const float* __restrict__ A,
          const float* __restrict__ B, const float* __restrict__ C,
          float* __restrict__ out)
{
    __shared__ SM sm;
    const int tid = threadIdx.x;
    const int i = tid;
    const uint32_t rank = ctarank();
    const uint32_t peer = rank ^ 1u;
    const int b = blockIdx.x >> 1;
    const uint32_t lS = smem_u32(&sm);

    if (tid == 0) {
        mbar_init(lS + MBA_OFF, 1);     mbar_init(lS + MBA_OFF + 8, 1);
        mbar_init(lS + MBB_OFF, 1);     mbar_init(lS + MBB_OFF + 8, 1);
        mbar_expect(lS + MBA_OFF, 1024); mbar_expect(lS + MBA_OFF + 8, 1024);
        mbar_expect(lS + MBB_OFF, 512);  mbar_expect(lS + MBB_OFF + 8, 512);
    }
    if (rank == 0 && tid < 128)
        ((uint32_t*)&sm.xs[0][0])[tid] = 0u;          // x_0 = 0

    // Weight registers: 128 half2 on both roles.
    //  CTA0: w0 = A[i][0:128), w1 = A[i][128:256)
    //  CTA1: w0 = B[i][0:128);  w1 = C[o][h*128 .. +128)  (o=i&127, h=i>>7)
    __half2 w0[64], w1[64];
    const int o = i & 127, h = i >> 7;
    if (rank == 0) {
        const float2* Ar = (const float2*)(A + (size_t)i * DST);
#pragma unroll
        for (int j = 0; j < 64; j++) { float2 v = Ar[j];      w0[j] = __floats2half2_rn(v.x, v.y); }
#pragma unroll
        for (int j = 0; j < 64; j++) { float2 v = Ar[64 + j]; w1[j] = __floats2half2_rn(v.x, v.y); }
    } else {
        const float2* Br = (const float2*)(B + (size_t)i * DIN);
#pragma unroll
        for (int j = 0; j < 64; j++) { float2 v = Br[j]; w0[j] = __floats2half2_rn(v.x, v.y); }
        const float2* Cr = (const float2*)(C + (size_t)o * DST + (h << 7));
#pragma unroll
        for (int j = 0; j < 64; j++) { float2 v = Cr[j]; w1[j] = __floats2half2_rn(v.x, v.y); }
    }

    __syncthreads();
    CLUSTER_SYNC();      // mbarriers armed on both CTAs before any st.async
    const uint32_t rS = mapa_u32(lS, peer);

    __half2 q[8];
    int ph[2] = {0, 0};

    if (rank == 0) {
        // ================= CTA0: recurrence engine =================
#pragma unroll 1
        for (int t = 0; t < T; ++t) {
            const int cur = t & 1, nxt = cur ^ 1;
            const __half* xc = sm.xs[cur];

            // Wait pBu(t) at the HEAD (fast-path; overlaps sibling warp's FMAs)
            const uint32_t mb = lS + MBA_OFF + (uint32_t)(cur * 8);
            mbar_wait(mb, ph[cur]); ph[cur] ^= 1;
            if (tid == 0) mbar_expect(mb, 1024);
            const float pbu = sm.pBu[cur][i];     // LDS hides under matvec

            ZERO8(q);
            MAC64(q, w0, xc);            // A[i][0:128) . x[0:128)
            MAC64(q, w1, xc + 128);      // A[i][128:256) . x[128:256)

            const float xv = tanh_fast(hsum8a(q) + pbu);
            const __half hx = __float2half_rn(xv);
            ((__half*)&sm.xs[nxt][0])[i] = hx;     // local publish: b16, no shfl

            const unsigned hv = (unsigned)__half_as_ushort(hx);
            const unsigned nb = __shfl_down_sync(0xffffffffu, hv, 1);
            if (!(i & 1))                          // remote ship (CTA1 has slack)
                st_async_b32(rS + XB_OFF + (uint32_t)(nxt * 512) + (uint32_t)(i << 1),
                             hv | (nb << 16), rS + MBB_OFF + (uint32_t)(nxt * 8));
            __syncthreads();
        }
    } else {
        // ================= CTA1: B.u producer + y consumer =================
        const float* ub = u + (size_t)b * T * DIN + o;   // threads i<128 load

        // Pre-loop: stage u_0, u_1; ship pBu(0), pBu(1)
        if (i < 128) {
            sm.us[0][i] = __float2half(ub[0]);
            sm.us[1][i] = __float2half(ub[DIN]);
        }
        __syncthreads();
        ZERO8(q); MAC64(q, w0, sm.us[0]);
        st_async_b32(rS + PBU_OFF + (uint32_t)(i << 2),
                     __float_as_uint(hsum8a(q)), rS + MBA_OFF);
        ZERO8(q); MAC64(q, w0, sm.us[1]);
        st_async_b32(rS + PBU_OFF + 1024u + (uint32_t)(i << 2),
                     __float_as_uint(hsum8a(q)), rS + MBA_OFF + 8u);
        __syncthreads();                                  // us reads done
        float un = (i < 128) ? ub[(size_t)2 * DIN] : 0.f; // u_2

#pragma unroll 1
        for (int k = 0; k < T; ++k) {
            const int cur = k & 1;
            if (i < 128) sm.us[cur][i] = __float2half(un);   // u_{k+2}
            __syncthreads();                                  // bar0

            ZERO8(q); MAC64(q, w0, sm.us[cur]);               // B . u_{k+2}
            const float pship = hsum8a(q);
            un = (i < 128 && k + 3 < T) ? ub[(size_t)(k + 3) * DIN] : 0.f;

            const int xsl = (k + 1) & 1;                      // wait x_{k+1}
            const uint32_t mb = lS + MBB_OFF + (uint32_t)(xsl * 8);
            mbar_wait(mb, ph[xsl]); ph[xsl] ^= 1;
            if (tid == 0) mbar_expect(mb, 512);

            const __half* xk = sm.xb[xsl] + (h << 7);
            ZERO8(q); MAC32(q, w1, xk);                       // C chunk 1 (64)
            float fy = hsum8a(q);
            ZERO8(q); MAC32(q, w1 + 32, xk + 64);             // C chunk 2 (64)
            fy += hsum8a(q);

            // Release token: pBu(k+2) ships only after our x_{k+1} reads
            if (k + 2 < T)
                st_async_b32(rS + PBU_OFF + (uint32_t)(cur * 1024) + (uint32_t)(i << 2),
                             __float_as_uint(pship), rS + MBA_OFF + (uint32_t)(cur * 8));

            if (h) sm.psC[o] = fy;
            __syncthreads();                                  // bar1
            if (!h) out[((size_t)b * T + k) * DOUT + o] = fy + sm.psC[o];
        }
    }
    CLUSTER_SYNC();      // no early exit while peer traffic may be in flight
}

// ---------------------------------------------------------------------------
// Single launch: 128 CTAs = 64 two-CTA clusters, one wave.
// ---------------------------------------------------------------------------
extern "C" void kernel_launch(void* const* d_in, const int* in_sizes, int n_in,
                              void* d_out, int out_size) {
    const float* u = (const float*)d_in[0];   // [64,4096,128]
    const float* A = (const float*)d_in[1];   // [256,256]
    const float* B = (const float*)d_in[2];   // [256,128]
    const float* C = (const float*)d_in[3];   // [128,256]
    float* out = (float*)d_out;               // [64,4096,128]

    ssm_fused<<<BATCH * 2, 256>>>(u, A, B, C, out);
}

// round 17
// speedup vs baseline: 1.0947x; 1.0947x over previous
#include <cuda_runtime.h>
#include <cuda_fp16.h>
#include <cstdint>
#include <cstddef>

#define BATCH 64
#define T     4096
#define DIN   128
#define DST   256
#define DOUT  128

// ---------------------------------------------------------------------------
// PTX helpers
// ---------------------------------------------------------------------------
__device__ __forceinline__ uint32_t ctarank() {
    uint32_t r; asm("mov.u32 %0, %%cluster_ctarank;" : "=r"(r)); return r;
}
__device__ __forceinline__ uint32_t smem_u32(const void* p) {
    uint32_t a;
    asm("{ .reg .u64 t; cvta.to.shared.u64 t, %1; cvt.u32.u64 %0, t; }"
        : "=r"(a) : "l"(p));
    return a;
}
__device__ __forceinline__ uint32_t mapa_u32(uint32_t l, uint32_t r) {
    uint32_t v; asm("mapa.shared::cluster.u32 %0, %1, %2;" : "=r"(v) : "r"(l), "r"(r));
    return v;
}
__device__ __forceinline__ void mbar_init(uint32_t m, uint32_t cnt) {
    asm volatile("mbarrier.init.shared.b64 [%0], %1;" :: "r"(m), "r"(cnt) : "memory");
}
__device__ __forceinline__ void mbar_expect(uint32_t m, uint32_t tx) {
    asm volatile("mbarrier.arrive.expect_tx.shared.b64 _, [%0], %1;"
                 :: "r"(m), "r"(tx) : "memory");
}
__device__ __forceinline__ void mbar_wait(uint32_t m, uint32_t parity) {
    asm volatile(
        "{\n\t.reg .pred P;\n\t"
        "W_%=:\n\t"
        "mbarrier.try_wait.parity.acquire.cluster.shared::cta.b64 P, [%0], %1, 0x989680;\n\t"
        "@!P bra W_%=;\n\t}"
        :: "r"(m), "r"(parity) : "memory");
}
__device__ __forceinline__ void st_async_b32(uint32_t raddr, uint32_t val, uint32_t rmbar) {
    asm volatile("st.async.shared::cluster.mbarrier::complete_tx::bytes.b32 [%0], %1, [%2];"
                 :: "r"(raddr), "r"(val), "r"(rmbar) : "memory");
}
#define CLUSTER_SYNC() do { \
    asm volatile("barrier.cluster.arrive.aligned;" ::: "memory"); \
    asm volatile("barrier.cluster.wait.aligned;"   ::: "memory"); \
} while (0)

// Exact identity tanh: 1 - 2/(1+e^{2s}).  |err| ~1e-6 (validated R11-R15).
__device__ __forceinline__ float tanh_fast(float s) {
    float e = __expf(2.0f * s);
    return 1.0f - __fdividef(2.0f, e + 1.0f);
}

// 64 HFMA2 over 128 halfs (16 uint4) into 8 half2 chains (8 adds each)
#define MAC64(ACC, W, XB) do {                                           \
    const uint4* xp_ = (const uint4*)(XB);                               \
    _Pragma("unroll")                                                    \
    for (int j_ = 0; j_ < 16; j_ += 2) {                                 \
        uint4 v0_ = xp_[j_], v1_ = xp_[j_ + 1];                          \
        (ACC)[0] = __hfma2((W)[4*j_+0], *(__half2*)&v0_.x, (ACC)[0]);    \
        (ACC)[1] = __hfma2((W)[4*j_+1], *(__half2*)&v0_.y, (ACC)[1]);    \
        (ACC)[2] = __hfma2((W)[4*j_+2], *(__half2*)&v0_.z, (ACC)[2]);    \
        (ACC)[3] = __hfma2((W)[4*j_+3], *(__half2*)&v0_.w, (ACC)[3]);    \
        (ACC)[4] = __hfma2((W)[4*j_+4], *(__half2*)&v1_.x, (ACC)[4]);    \
        (ACC)[5] = __hfma2((W)[4*j_+5], *(__half2*)&v1_.y, (ACC)[5]);    \
        (ACC)[6] = __hfma2((W)[4*j_+6], *(__half2*)&v1_.z, (ACC)[6]);    \
        (ACC)[7] = __hfma2((W)[4*j_+7], *(__half2*)&v1_.w, (ACC)[7]);    \
    } } while (0)

#define ZERO8(ACC) do { _Pragma("unroll") \
    for (int k_ = 0; k_ < 8; k_++) (ACC)[k_] = __float2half2_rn(0.f); } while (0)

__device__ __forceinline__ float hsum8a(const __half2* q) {
    float2 a0 = __half22float2(q[0]), a1 = __half22float2(q[1]);
    float2 a2 = __half22float2(q[2]), a3 = __half22float2(q[3]);
    float2 a4 = __half22float2(q[4]), a5 = __half22float2(q[5]);
    float2 a6 = __half22float2(q[6]), a7 = __half22float2(q[7]);
    return (((a0.x+a0.y)+(a1.x+a1.y)) + ((a2.x+a2.y)+(a3.x+a3.y)))
         + (((a4.x+a4.y)+(a5.x+a5.y)) + ((a6.x+a6.y)+(a7.x+a7.y)));
}

// Shared layout (identical on both CTAs; fixed offsets for remote addressing)
struct __align__(16) SM {
    __half xs[2][256];             // CTA0: local x ring            1024 B
    __half xb[4][256];             // CTA1: received x ring (4-deep) 2048 B
    __half us[2][128];             // CTA1: u staging (parity)       512 B
    float  pBu[4][256];            // CTA0: received B.u ring (4)   4096 B
    float  psC[2][128];            // CTA1: y half-combine (parity) 1024 B
    unsigned long long mbA[4];     // CTA0: pBu arrival (per slot)
    unsigned long long mbB[4];     // CTA1: x arrival   (per slot)
};
#define XB_OFF   ((uint32_t)offsetof(SM, xb))
#define PBU_OFF  ((uint32_t)offsetof(SM, pBu))
#define MBA_OFF  ((uint32_t)offsetof(SM, mbA))
#define MBB_OFF  ((uint32_t)offsetof(SM, mbB))

// ---------------------------------------------------------------------------
// Pipelined-role SSM, 4-deep rings:
// CTA0 (recurrence engine): thread i holds the FULL A row (128 half2 regs).
//   step t: wait pBu(t) [slot t&3, ~1600 cyc slack -> pure fast-path] ->
//   A.x_t (128 HFMA2, local xs ring) -> tanh -> b16 local publish ->
//   shfl+st.async x_{t+1} into CTA1's xb slot (t+1)&3 -> bar.
//   Token chain: wait pBu(t) certifies CTA1 read x_{t-3} => xb slot (t+1)&3
//   (previous occupant x_{t-3}) is free, and pBu slot t&3 may be re-armed.
// CTA1 (co-processor), ONE bar per iter: B.u_{k+4} (u staged one iter early,
//   parity ring) -> wait x_{k+1} [slot (k+1)&3] -> ship pBu(k+4) (release
//   token) -> y_k = C.x_{k+1} (single MAC64 + one hsum) -> psC parity combine
//   -> bar -> y store.  Pre-loop ships pBu(0..3).
// ---------------------------------------------------------------------------
__global__ void __launch_bounds__(256, 1) __cluster_dims__(2, 1, 1)
ssm_fused(const float* __restrict__ u, const float* __restrict__ A,
          const float* __restrict__ B, const float* __restrict__ C,
          float* __restrict__ out)
{
    __shared__ SM sm;
    const int tid = threadIdx.x;
    const int i = tid;
    const uint32_t rank = ctarank();
    const uint32_t peer = rank ^ 1u;
    const int b = blockIdx.x >> 1;
    const uint32_t lS = smem_u32(&sm);

    if (tid == 0) {
#pragma unroll
        for (int s = 0; s < 4; s++) {
            mbar_init(lS + MBA_OFF + s * 8, 1); mbar_expect(lS + MBA_OFF + s * 8, 1024);
            mbar_init(lS + MBB_OFF + s * 8, 1); mbar_expect(lS + MBB_OFF + s * 8, 512);
        }
    }
    if (rank == 0 && tid < 128)
        ((uint32_t*)&sm.xs[0][0])[tid] = 0u;          // x_0 = 0

    // Weight registers: 128 half2 on both roles.
    //  CTA0: w0 = A[i][0:128), w1 = A[i][128:256)
    //  CTA1: w0 = B[i][0:128);  w1 = C[o][h*128 .. +128)  (o=i&127, h=i>>7)
    __half2 w0[64], w1[64];
    const int o = i & 127, h = i >> 7;
    if (rank == 0) {
        const float2* Ar = (const float2*)(A + (size_t)i * DST);
#pragma unroll
        for (int j = 0; j < 64; j++) { float2 v = Ar[j];      w0[j] = __floats2half2_rn(v.x, v.y); }
#pragma unroll
        for (int j = 0; j < 64; j++) { float2 v = Ar[64 + j]; w1[j] = __floats2half2_rn(v.x, v.y); }
    } else {
        const float2* Br = (const float2*)(B + (size_t)i * DIN);
#pragma unroll
        for (int j = 0; j < 64; j++) { float2 v = Br[j]; w0[j] = __floats2half2_rn(v.x, v.y); }
        const float2* Cr = (const float2*)(C + (size_t)o * DST + (h << 7));
#pragma unroll
        for (int j = 0; j < 64; j++) { float2 v = Cr[j]; w1[j] = __floats2half2_rn(v.x, v.y); }
    }

    __syncthreads();
    CLUSTER_SYNC();      // mbarriers armed on both CTAs before any st.async
    const uint32_t rS = mapa_u32(lS, peer);

    __half2 q[8];
    int ph[4] = {0, 0, 0, 0};

    if (rank == 0) {
        // ================= CTA0: recurrence engine =================
#pragma unroll 1
        for (int t = 0; t < T; ++t) {
            const int cur = t & 1, nxt = cur ^ 1;
            const int sl = t & 3;
            const __half* xc = sm.xs[cur];

            // pBu(t): 4-deep queue -> always fast-path
            const uint32_t mb = lS + MBA_OFF + (uint32_t)(sl * 8);
            mbar_wait(mb, ph[sl]); ph[sl] ^= 1;
            if (tid == 0) mbar_expect(mb, 1024);
            const float pbu = sm.pBu[sl][i];      // LDS hides under matvec

            ZERO8(q);
            MAC64(q, w0, xc);            // A[i][0:128) . x[0:128)
            MAC64(q, w1, xc + 128);      // A[i][128:256) . x[128:256)

            const float xv = tanh_fast(hsum8a(q) + pbu);
            const __half hx = __float2half_rn(xv);
            ((__half*)&sm.xs[nxt][0])[i] = hx;     // local publish: b16, no shfl

            const unsigned hv = (unsigned)__half_as_ushort(hx);
            const unsigned nb = __shfl_down_sync(0xffffffffu, hv, 1);
            if (!(i & 1)) {                        // ship x_{t+1} -> xb slot (t+1)&3
                const int xsl = (t + 1) & 3;
                st_async_b32(rS + XB_OFF + (uint32_t)(xsl * 512) + (uint32_t)(i << 1),
                             hv | (nb << 16), rS + MBB_OFF + (uint32_t)(xsl * 8));
            }
            __syncthreads();
        }
    } else {
        // ================= CTA1: B.u producer + y consumer =================
        const float* ub = u + (size_t)b * T * DIN + o;   // threads i<128 load

        // Pre-loop: ship pBu(0..3) (slots initially free; mbarriers armed)
#pragma unroll 1
        for (int j = 0; j < 4; j++) {
            if (i < 128) sm.us[0][i] = __float2half(ub[(size_t)j * DIN]);
            __syncthreads();
            ZERO8(q); MAC64(q, w0, sm.us[0]);
            st_async_b32(rS + PBU_OFF + (uint32_t)(j * 1024) + (uint32_t)(i << 2),
                         __float_as_uint(hsum8a(q)), rS + MBA_OFF + (uint32_t)(j * 8));
            __syncthreads();                       // us[0] reads done
        }
        // Prime u ring: us[0] = u_4; un = u_5
        if (i < 128) sm.us[0][i] = __float2half(ub[(size_t)4 * DIN]);
        float un = (i < 128) ? ub[(size_t)5 * DIN] : 0.f;
        __syncthreads();

#pragma unroll 1
        for (int k = 0; k < T; ++k) {
            const int cur = k & 1;

            // B . u_{k+4} from us[cur]; stage u_{k+5} into us[cur^1]
            ZERO8(q); MAC64(q, w0, sm.us[cur]);
            const float pship = hsum8a(q);
            if (i < 128) sm.us[cur ^ 1][i] = __float2half(un);
            un = (i < 128 && k + 6 < T) ? ub[(size_t)(k + 6) * DIN] : 0.f;

            // Wait x_{k+1} (slot (k+1)&3)
            const int xsl = (k + 1) & 3;
            const uint32_t mb = lS + MBB_OFF + (uint32_t)(xsl * 8);
            mbar_wait(mb, ph[xsl]); ph[xsl] ^= 1;
            if (tid == 0) mbar_expect(mb, 512);

            // Release token: pBu(k+4) ships only after our x_{k+1} receipt
            if (k + 4 < T)
                st_async_b32(rS + PBU_OFF + (uint32_t)((k & 3) * 1024) + (uint32_t)(i << 2),
                             __float_as_uint(pship), rS + MBA_OFF + (uint32_t)((k & 3) * 8));

            // y_k = C . x_{k+1}: one 128-half chunk per thread, one hsum
            ZERO8(q); MAC64(q, w1, sm.xb[xsl] + (h << 7));
            const float fy = hsum8a(q);

            if (h) sm.psC[cur][o] = fy;
            __syncthreads();                       // the ONLY per-iter barrier
            if (!h) out[((size_t)b * T + k) * DOUT + o] = fy + sm.psC[cur][o];
        }
    }
    CLUSTER_SYNC();      // no early exit while peer traffic may be in flight
}

// ---------------------------------------------------------------------------
// Single launch: 128 CTAs = 64 two-CTA clusters, one wave.
// ---------------------------------------------------------------------------
extern "C" void kernel_launch(void* const* d_in, const int* in_sizes, int n_in,
                              void* d_out, int out_size) {
    const float* u = (const float*)d_in[0];   // [64,4096,128]
    const float* A = (const float*)d_in[1];   // [256,256]
    const float* B = (const float*)d_in[2];   // [256,128]
    const float* C = (const float*)d_in[3];   // [128,256]
    float* out = (float*)d_out;               // [64,4096,128]

    ssm_fused<<<BATCH * 2, 256>>>(u, A, B, C, out);
}